// round 1
// baseline (speedup 1.0000x reference)
#include <cuda_runtime.h>
#include <cuda_bf16.h>
#include <cstdint>

// ---------------------------------------------------------------------------
// RNN: out[b,t,:] = sigmoid(x@K + h_{t-1}@Wr),  B=64, T=512, D=H=1024
// Phase 1: xh = x @ kernel   (TF32 mma.sync GEMM, 32768x1024x1024)
// Phase 2: 512 sequential step kernels; h_{t-1} read from d_out[:, t-1, :]
// ---------------------------------------------------------------------------

#define BATCH 64
#define TSEQ  512
#define DIM   1024

// 128 MB scratch for xh (allocation-free: __device__ global)
__device__ float g_xh[(size_t)BATCH * TSEQ * DIM];

__device__ __forceinline__ uint32_t f2tf32(float x) {
    uint32_t r;
    asm("cvt.rna.tf32.f32 %0, %1;" : "=r"(r) : "f"(x));
    return r;
}

__device__ __forceinline__ void mma_tf32(float* d,
                                         uint32_t a0, uint32_t a1, uint32_t a2, uint32_t a3,
                                         uint32_t b0, uint32_t b1) {
    asm volatile(
        "mma.sync.aligned.m16n8k8.row.col.f32.tf32.tf32.f32 "
        "{%0,%1,%2,%3}, {%4,%5,%6,%7}, {%8,%9}, {%0,%1,%2,%3};\n"
        : "+f"(d[0]), "+f"(d[1]), "+f"(d[2]), "+f"(d[3])
        : "r"(a0), "r"(a1), "r"(a2), "r"(a3), "r"(b0), "r"(b1));
}

__device__ __forceinline__ float sigmoidf_fast(float z) {
    return 1.0f / (1.0f + __expf(-z));
}

// ---------------------------------------------------------------------------
// Phase 1: xh = X[32768,1024] @ W[1024,1024]  (row-major both)
// CTA tile 128(M) x 64(N), BK=32. 256 threads = 8 warps, warp grid 4(M) x 2(N),
// warp tile 32x32 = 2 m16 x 4 n8 mma tiles.
// ---------------------------------------------------------------------------
__global__ __launch_bounds__(256) void gemm_xh_kernel(const float* __restrict__ X,
                                                      const float* __restrict__ W) {
    __shared__ uint32_t As[128][36];  // [m][k], pad 36: conflict-free frag loads
    __shared__ uint32_t Bs[32][68];   // [k][n], pad 68

    const int tid  = threadIdx.x;
    const int lane = tid & 31;
    const int wid  = tid >> 5;
    const int bm   = blockIdx.y * 128;
    const int bn   = blockIdx.x * 64;
    const int wm   = (wid & 3) * 32;
    const int wn   = (wid >> 2) * 32;
    const int gid  = lane >> 2;   // 0..7
    const int tg   = lane & 3;    // 0..3

    float acc[2][4][4];
    #pragma unroll
    for (int mt = 0; mt < 2; mt++)
        #pragma unroll
        for (int nt = 0; nt < 4; nt++)
            #pragma unroll
            for (int i = 0; i < 4; i++) acc[mt][nt][i] = 0.0f;

    for (int k0 = 0; k0 < DIM; k0 += 32) {
        // Load A tile: 128x32 floats = 1024 float4, 4 per thread
        #pragma unroll
        for (int i = 0; i < 4; i++) {
            int idx = tid + i * 256;
            int r = idx >> 3;
            int c = (idx & 7) * 4;
            float4 v = *(const float4*)(X + (size_t)(bm + r) * DIM + k0 + c);
            As[r][c + 0] = f2tf32(v.x);
            As[r][c + 1] = f2tf32(v.y);
            As[r][c + 2] = f2tf32(v.z);
            As[r][c + 3] = f2tf32(v.w);
        }
        // Load B tile: 32x64 floats = 512 float4, 2 per thread
        #pragma unroll
        for (int i = 0; i < 2; i++) {
            int idx = tid + i * 256;
            int r = idx >> 4;
            int c = (idx & 15) * 4;
            float4 v = *(const float4*)(W + (size_t)(k0 + r) * DIM + bn + c);
            Bs[r][c + 0] = f2tf32(v.x);
            Bs[r][c + 1] = f2tf32(v.y);
            Bs[r][c + 2] = f2tf32(v.z);
            Bs[r][c + 3] = f2tf32(v.w);
        }
        __syncthreads();

        #pragma unroll
        for (int k8 = 0; k8 < 32; k8 += 8) {
            uint32_t a[2][4], b[4][2];
            #pragma unroll
            for (int mt = 0; mt < 2; mt++) {
                int r = wm + mt * 16 + gid;
                a[mt][0] = As[r][k8 + tg];
                a[mt][1] = As[r + 8][k8 + tg];
                a[mt][2] = As[r][k8 + tg + 4];
                a[mt][3] = As[r + 8][k8 + tg + 4];
            }
            #pragma unroll
            for (int nt = 0; nt < 4; nt++) {
                int c = wn + nt * 8 + gid;
                b[nt][0] = Bs[k8 + tg][c];
                b[nt][1] = Bs[k8 + tg + 4][c];
            }
            #pragma unroll
            for (int mt = 0; mt < 2; mt++)
                #pragma unroll
                for (int nt = 0; nt < 4; nt++)
                    mma_tf32(acc[mt][nt], a[mt][0], a[mt][1], a[mt][2], a[mt][3],
                             b[nt][0], b[nt][1]);
        }
        __syncthreads();
    }

    // Epilogue -> g_xh
    #pragma unroll
    for (int mt = 0; mt < 2; mt++) {
        #pragma unroll
        for (int nt = 0; nt < 4; nt++) {
            int r = bm + wm + mt * 16 + gid;
            int c = bn + wn + nt * 8 + tg * 2;
            float2 v0 = make_float2(acc[mt][nt][0], acc[mt][nt][1]);
            float2 v1 = make_float2(acc[mt][nt][2], acc[mt][nt][3]);
            *(float2*)(&g_xh[(size_t)r * DIM + c])       = v0;
            *(float2*)(&g_xh[(size_t)(r + 8) * DIM + c]) = v1;
        }
    }
}

// ---------------------------------------------------------------------------
// Phase 2: one timestep.
// h_t[:, bn:bn+32] = sigmoid(xh[:,t,tile] + h_{t-1} @ Wr[:, tile])
// h_{t-1} is read from OUT[:, t-1, :]; t==0 uses h=0 (skip matmul).
// Grid: 32 CTAs (N tiles of 32). CTA tile 64(M=all batches) x 32(N), BK=32.
// 256 threads = 8 warps: warp grid 4(M) x 2(N), warp tile 16x16 = 1 m16 x 2 n8.
// ---------------------------------------------------------------------------
__global__ __launch_bounds__(256) void rnn_step_kernel(const float* __restrict__ Wr,
                                                       float* __restrict__ OUT,
                                                       int t) {
    __shared__ uint32_t As[64][36];  // h_prev tile [b][k]
    __shared__ uint32_t Bs[32][36];  // Wr tile [k][n]

    const int tid  = threadIdx.x;
    const int lane = tid & 31;
    const int wid  = tid >> 5;
    const int bn   = blockIdx.x * 32;
    const int wm   = (wid & 3) * 16;
    const int wn   = (wid >> 2) * 16;
    const int gid  = lane >> 2;
    const int tg   = lane & 3;

    float acc[2][4];
    #pragma unroll
    for (int nt = 0; nt < 2; nt++)
        #pragma unroll
        for (int i = 0; i < 4; i++) acc[nt][i] = 0.0f;

    if (t > 0) {
        const float* Hprev = OUT + (size_t)(t - 1) * DIM;  // + b*TSEQ*DIM per row
        for (int k0 = 0; k0 < DIM; k0 += 32) {
            // A: 64x32 floats = 512 float4, 2 per thread
            #pragma unroll
            for (int i = 0; i < 2; i++) {
                int idx = tid + i * 256;
                int r = idx >> 3;
                int c = (idx & 7) * 4;
                float4 v = *(const float4*)(Hprev + (size_t)r * (TSEQ * DIM) + k0 + c);
                As[r][c + 0] = f2tf32(v.x);
                As[r][c + 1] = f2tf32(v.y);
                As[r][c + 2] = f2tf32(v.z);
                As[r][c + 3] = f2tf32(v.w);
            }
            // B: 32x32 floats = 256 float4, 1 per thread
            {
                int r = tid >> 3;
                int c = (tid & 7) * 4;
                float4 v = *(const float4*)(Wr + (size_t)(k0 + r) * DIM + bn + c);
                Bs[r][c + 0] = f2tf32(v.x);
                Bs[r][c + 1] = f2tf32(v.y);
                Bs[r][c + 2] = f2tf32(v.z);
                Bs[r][c + 3] = f2tf32(v.w);
            }
            __syncthreads();

            #pragma unroll
            for (int k8 = 0; k8 < 32; k8 += 8) {
                int r = wm + gid;
                uint32_t a0 = As[r][k8 + tg];
                uint32_t a1 = As[r + 8][k8 + tg];
                uint32_t a2 = As[r][k8 + tg + 4];
                uint32_t a3 = As[r + 8][k8 + tg + 4];
                #pragma unroll
                for (int nt = 0; nt < 2; nt++) {
                    int c = wn + nt * 8 + gid;
                    uint32_t b0 = Bs[k8 + tg][c];
                    uint32_t b1 = Bs[k8 + tg + 4][c];
                    mma_tf32(acc[nt], a0, a1, a2, a3, b0, b1);
                }
            }
            __syncthreads();
        }
    }

    // Epilogue: z = acc + xh[b,t,c]; out[b,t,c] = sigmoid(z)
    #pragma unroll
    for (int nt = 0; nt < 2; nt++) {
        int r = wm + gid;             // batch row
        int c = bn + wn + nt * 8 + tg * 2;
        size_t o0 = ((size_t)r * TSEQ + t) * DIM + c;
        size_t o8 = ((size_t)(r + 8) * TSEQ + t) * DIM + c;
        float z0 = acc[nt][0] + g_xh[o0];
        float z1 = acc[nt][1] + g_xh[o0 + 1];
        float z2 = acc[nt][2] + g_xh[o8];
        float z3 = acc[nt][3] + g_xh[o8 + 1];
        OUT[o0]     = sigmoidf_fast(z0);
        OUT[o0 + 1] = sigmoidf_fast(z1);
        OUT[o8]     = sigmoidf_fast(z2);
        OUT[o8 + 1] = sigmoidf_fast(z3);
    }
}

// ---------------------------------------------------------------------------
extern "C" void kernel_launch(void* const* d_in, const int* in_sizes, int n_in,
                              void* d_out, int out_size) {
    const float* x  = (const float*)d_in[0];  // [64, 512, 1024]
    const float* w  = (const float*)d_in[1];  // [1024, 1024]
    const float* wr = (const float*)d_in[2];  // [1024, 1024]
    float* out = (float*)d_out;               // [64, 512, 1024]

    // Phase 1: xh = x @ w
    dim3 grid1(DIM / 64, (BATCH * TSEQ) / 128);
    gemm_xh_kernel<<<grid1, 256>>>(x, w);

    // Phase 2: sequential recurrence, 512 step kernels (stream-ordered)
    for (int t = 0; t < TSEQ; t++) {
        rnn_step_kernel<<<DIM / 32, 256>>>(wr, out, t);
    }
}

// round 2
// speedup vs baseline: 4.8026x; 4.8026x over previous
#include <cuda_runtime.h>
#include <cuda_bf16.h>
#include <cstdint>

// ---------------------------------------------------------------------------
// RNN: out[b,t,:] = sigmoid(x@K + h_{t-1}@Wr),  B=64, T=512, D=H=1024
// Phase 1: xh = x @ kernel (TF32 mma GEMM, 32768x1024x1024) -> g_xh
// Phase 2: ONE persistent kernel, 64 CTAs, 512 steps with grid barriers.
//          Wr slice lives in SMEM per CTA; h_prev streamed via cp.async.
// ---------------------------------------------------------------------------

#define BATCH 64
#define TSEQ  512
#define DIM   1024

#define NCTA   64
#define NTILE  16                 // N columns per CTA
#define BK     128                // K chunk for h_prev streaming
#define NCHUNK (DIM / BK)         // 8
#define AS_STRIDE 132             // words per A row (128 + 4 pad, 16B-multiple)
#define BS_STRIDE 1028            // words per B row (1024 + 4 pad)
#define AS_WORDS  (2 * 64 * AS_STRIDE)     // double-buffered 64xBK
#define BS_WORDS  (NTILE * BS_STRIDE)
#define SMEM_BYTES ((AS_WORDS + BS_WORDS) * 4)   // 133,376 B

__device__ float g_xh[(size_t)BATCH * TSEQ * DIM];
__device__ unsigned g_count;   // barrier arrivals (returns to 0 every round)
__device__ unsigned g_sense;   // barrier sense (512 even rounds -> returns to 0)

__device__ __forceinline__ uint32_t f2tf32(float x) {
    uint32_t r;
    asm("cvt.rna.tf32.f32 %0, %1;" : "=r"(r) : "f"(x));
    return r;
}

__device__ __forceinline__ void mma_tf32(float* d,
                                         uint32_t a0, uint32_t a1, uint32_t a2, uint32_t a3,
                                         uint32_t b0, uint32_t b1) {
    asm volatile(
        "mma.sync.aligned.m16n8k8.row.col.f32.tf32.tf32.f32 "
        "{%0,%1,%2,%3}, {%4,%5,%6,%7}, {%8,%9}, {%0,%1,%2,%3};\n"
        : "+f"(d[0]), "+f"(d[1]), "+f"(d[2]), "+f"(d[3])
        : "r"(a0), "r"(a1), "r"(a2), "r"(a3), "r"(b0), "r"(b1));
}

__device__ __forceinline__ float sigmoidf_fast(float z) {
    return 1.0f / (1.0f + __expf(-z));
}

// ---------------------------------------------------------------------------
// Phase 1: xh = X[32768,1024] @ W[1024,1024]
// ---------------------------------------------------------------------------
__global__ __launch_bounds__(256) void gemm_xh_kernel(const float* __restrict__ X,
                                                      const float* __restrict__ W) {
    __shared__ uint32_t As[128][36];
    __shared__ uint32_t Bs[32][68];

    const int tid  = threadIdx.x;
    const int lane = tid & 31;
    const int wid  = tid >> 5;
    const int bm   = blockIdx.y * 128;
    const int bn   = blockIdx.x * 64;
    const int wm   = (wid & 3) * 32;
    const int wn   = (wid >> 2) * 32;
    const int gid  = lane >> 2;
    const int tg   = lane & 3;

    float acc[2][4][4];
    #pragma unroll
    for (int mt = 0; mt < 2; mt++)
        #pragma unroll
        for (int nt = 0; nt < 4; nt++)
            #pragma unroll
            for (int i = 0; i < 4; i++) acc[mt][nt][i] = 0.0f;

    for (int k0 = 0; k0 < DIM; k0 += 32) {
        #pragma unroll
        for (int i = 0; i < 4; i++) {
            int idx = tid + i * 256;
            int r = idx >> 3;
            int c = (idx & 7) * 4;
            float4 v = *(const float4*)(X + (size_t)(bm + r) * DIM + k0 + c);
            As[r][c + 0] = f2tf32(v.x);
            As[r][c + 1] = f2tf32(v.y);
            As[r][c + 2] = f2tf32(v.z);
            As[r][c + 3] = f2tf32(v.w);
        }
        #pragma unroll
        for (int i = 0; i < 2; i++) {
            int idx = tid + i * 256;
            int r = idx >> 4;
            int c = (idx & 15) * 4;
            float4 v = *(const float4*)(W + (size_t)(k0 + r) * DIM + bn + c);
            Bs[r][c + 0] = f2tf32(v.x);
            Bs[r][c + 1] = f2tf32(v.y);
            Bs[r][c + 2] = f2tf32(v.z);
            Bs[r][c + 3] = f2tf32(v.w);
        }
        __syncthreads();

        #pragma unroll
        for (int k8 = 0; k8 < 32; k8 += 8) {
            uint32_t a[2][4], b[4][2];
            #pragma unroll
            for (int mt = 0; mt < 2; mt++) {
                int r = wm + mt * 16 + gid;
                a[mt][0] = As[r][k8 + tg];
                a[mt][1] = As[r + 8][k8 + tg];
                a[mt][2] = As[r][k8 + tg + 4];
                a[mt][3] = As[r + 8][k8 + tg + 4];
            }
            #pragma unroll
            for (int nt = 0; nt < 4; nt++) {
                int c = wn + nt * 8 + gid;
                b[nt][0] = Bs[k8 + tg][c];
                b[nt][1] = Bs[k8 + tg + 4][c];
            }
            #pragma unroll
            for (int mt = 0; mt < 2; mt++)
                #pragma unroll
                for (int nt = 0; nt < 4; nt++)
                    mma_tf32(acc[mt][nt], a[mt][0], a[mt][1], a[mt][2], a[mt][3],
                             b[nt][0], b[nt][1]);
        }
        __syncthreads();
    }

    #pragma unroll
    for (int mt = 0; mt < 2; mt++) {
        #pragma unroll
        for (int nt = 0; nt < 4; nt++) {
            int r = bm + wm + mt * 16 + gid;
            int c = bn + wn + nt * 8 + tg * 2;
            float2 v0 = make_float2(acc[mt][nt][0], acc[mt][nt][1]);
            float2 v1 = make_float2(acc[mt][nt][2], acc[mt][nt][3]);
            *(float2*)(&g_xh[(size_t)r * DIM + c])       = v0;
            *(float2*)(&g_xh[(size_t)(r + 8) * DIM + c]) = v1;
        }
    }
}

// ---------------------------------------------------------------------------
// Phase 2: persistent recurrence kernel.
// Grid = 64 CTAs x 256 thr. CTA owns N-tile of 16 cols; Wr slice in SMEM.
// Warp grid 4(M)x2(N), warp tile 16x8 (one m16n8k8 mma per k8).
// ---------------------------------------------------------------------------
__global__ __launch_bounds__(256, 1) void rnn_persistent(const float* __restrict__ Wr,
                                                         float* __restrict__ OUT) {
    extern __shared__ uint32_t smem[];
    uint32_t* Bs = smem;               // [NTILE][BS_STRIDE]  Wr slice (tf32)
    uint32_t* As = smem + BS_WORDS;    // [2][64][AS_STRIDE]  h_prev chunks (raw f32)

    const int tid  = threadIdx.x;
    const int lane = tid & 31;
    const int wid  = tid >> 5;
    const int bn   = blockIdx.x * NTILE;
    const int wm   = (wid & 3) * 16;
    const int wn   = (wid >> 2) * 8;
    const int gid  = lane >> 2;
    const int tg   = lane & 3;

    // Load this CTA's Wr slice into SMEM, transposed to [n][k], tf32-rounded.
    for (int idx = tid; idx < NTILE * DIM; idx += 256) {
        int n = idx & (NTILE - 1);
        int k = idx >> 4;
        Bs[n * BS_STRIDE + k] = f2tf32(Wr[(size_t)k * DIM + bn + n]);
    }
    __syncthreads();

    const int arow  = (wm + gid) * AS_STRIDE;
    const int brow0 = (wn + gid) * BS_STRIDE;

    for (int t = 0; t < TSEQ; t++) {
        float acc[4] = {0.0f, 0.0f, 0.0f, 0.0f};

        if (t > 0) {
            const float* Hprev = OUT + (size_t)(t - 1) * DIM;  // + r*TSEQ*DIM per batch row

            // Prefetch chunk 0
            {
                uint32_t* dst = As;
                #pragma unroll
                for (int i = 0; i < 8; i++) {
                    int idx = tid + i * 256;
                    int r = idx >> 5;
                    int c4 = idx & 31;
                    const float* src = Hprev + (size_t)r * (TSEQ * DIM) + c4 * 4;
                    uint32_t da = (uint32_t)__cvta_generic_to_shared(dst + r * AS_STRIDE + c4 * 4);
                    asm volatile("cp.async.cg.shared.global [%0], [%1], 16;\n" :: "r"(da), "l"(src));
                }
                asm volatile("cp.async.commit_group;\n" ::: "memory");
            }

            for (int c = 0; c < NCHUNK; c++) {
                if (c + 1 < NCHUNK) {
                    uint32_t* dst = As + ((c + 1) & 1) * (64 * AS_STRIDE);
                    int k0 = (c + 1) * BK;
                    #pragma unroll
                    for (int i = 0; i < 8; i++) {
                        int idx = tid + i * 256;
                        int r = idx >> 5;
                        int c4 = idx & 31;
                        const float* src = Hprev + (size_t)r * (TSEQ * DIM) + k0 + c4 * 4;
                        uint32_t da = (uint32_t)__cvta_generic_to_shared(dst + r * AS_STRIDE + c4 * 4);
                        asm volatile("cp.async.cg.shared.global [%0], [%1], 16;\n" :: "r"(da), "l"(src));
                    }
                    asm volatile("cp.async.commit_group;\n" ::: "memory");
                    asm volatile("cp.async.wait_group 1;\n" ::: "memory");
                } else {
                    asm volatile("cp.async.wait_group 0;\n" ::: "memory");
                }
                __syncthreads();

                const uint32_t* Ab = As + (c & 1) * (64 * AS_STRIDE);
                const int kbase = c * BK;
                #pragma unroll
                for (int k8 = 0; k8 < BK; k8 += 8) {
                    uint32_t a0 = f2tf32(__uint_as_float(Ab[arow + k8 + tg]));
                    uint32_t a1 = f2tf32(__uint_as_float(Ab[arow + 8 * AS_STRIDE + k8 + tg]));
                    uint32_t a2 = f2tf32(__uint_as_float(Ab[arow + k8 + tg + 4]));
                    uint32_t a3 = f2tf32(__uint_as_float(Ab[arow + 8 * AS_STRIDE + k8 + tg + 4]));
                    uint32_t b0 = Bs[brow0 + kbase + k8 + tg];
                    uint32_t b1 = Bs[brow0 + kbase + k8 + tg + 4];
                    mma_tf32(acc, a0, a1, a2, a3, b0, b1);
                }
                __syncthreads();
            }
        }

        // Epilogue: h = sigmoid(acc + xh[b,t,c]) -> OUT[b,t,c]
        {
            int rb = wm + gid;
            int cb = bn + wn + 2 * tg;
            size_t o0 = ((size_t)rb * TSEQ + t) * DIM + cb;
            size_t o8 = o0 + (size_t)8 * TSEQ * DIM;
            float2 xh0 = *(const float2*)&g_xh[o0];
            float2 xh1 = *(const float2*)&g_xh[o8];
            float2 h0 = make_float2(sigmoidf_fast(acc[0] + xh0.x),
                                    sigmoidf_fast(acc[1] + xh0.y));
            float2 h1 = make_float2(sigmoidf_fast(acc[2] + xh1.x),
                                    sigmoidf_fast(acc[3] + xh1.y));
            *(float2*)&OUT[o0] = h0;
            *(float2*)&OUT[o8] = h1;
        }

        // Grid barrier (sense-reversing; 512 even rounds -> state returns to 0,
        // keeping g_count/g_sense invariant across graph replays).
        __syncthreads();
        if (tid == 0) {
            unsigned ns = ((unsigned)t & 1u) ^ 1u;   // 1,0,1,0,...
            unsigned old;
            asm volatile("atom.acq_rel.gpu.global.add.u32 %0, [%1], %2;"
                         : "=r"(old) : "l"(&g_count), "r"(1u) : "memory");
            if (old == NCTA - 1) {
                asm volatile("st.relaxed.gpu.global.u32 [%0], %1;"
                             :: "l"(&g_count), "r"(0u) : "memory");
                asm volatile("st.release.gpu.global.u32 [%0], %1;"
                             :: "l"(&g_sense), "r"(ns) : "memory");
            } else {
                unsigned v;
                do {
                    asm volatile("ld.acquire.gpu.global.u32 %0, [%1];"
                                 : "=r"(v) : "l"(&g_sense) : "memory");
                } while (v != ns);
            }
        }
        __syncthreads();
    }
}

// ---------------------------------------------------------------------------
extern "C" void kernel_launch(void* const* d_in, const int* in_sizes, int n_in,
                              void* d_out, int out_size) {
    const float* x  = (const float*)d_in[0];  // [64, 512, 1024]
    const float* w  = (const float*)d_in[1];  // [1024, 1024]
    const float* wr = (const float*)d_in[2];  // [1024, 1024]
    float* out = (float*)d_out;               // [64, 512, 1024]

    // Phase 1: xh = x @ w
    dim3 grid1(DIM / 64, (BATCH * TSEQ) / 128);
    gemm_xh_kernel<<<grid1, 256>>>(x, w);

    // Phase 2: persistent recurrence (single launch, grid-wide barriers)
    cudaFuncSetAttribute(rnn_persistent,
                         cudaFuncAttributeMaxDynamicSharedMemorySize, SMEM_BYTES);
    rnn_persistent<<<NCTA, 256, SMEM_BYTES>>>(wr, out);
}

// round 3
// speedup vs baseline: 5.4160x; 1.1277x over previous
#include <cuda_runtime.h>
#include <cuda_bf16.h>
#include <cstdint>

// ---------------------------------------------------------------------------
// RNN: out[b,t,:] = sigmoid(x@K + h_{t-1}@Wr),  B=64, T=512, D=H=1024
// Phase 1: xh = x @ kernel  -- double-buffered cp.async TF32 mma GEMM
// Phase 2: ONE persistent kernel, 64 CTAs, 512 steps with grid barriers.
//          Wr slice in SMEM; h_prev streamed (4-slot ring); 2-way K-split.
// ---------------------------------------------------------------------------

#define BATCH 64
#define TSEQ  512
#define DIM   1024

// ---- phase 2 geometry ----
#define NCTA   64
#define NTILE  16
#define BK     128                   // chunk width
#define AS_STRIDE 132                // 128 + 4 pad (16B multiple)
#define BS_STRIDE 1028               // 1024 + 4 pad
#define AS_SLOT   (64 * AS_STRIDE)   // words per chunk slot
#define BS_WORDS  (NTILE * BS_STRIDE)
#define P2_SMEM_BYTES ((BS_WORDS + 4 * AS_SLOT) * 4)   // 200,960 B

// ---- phase 1 geometry ----
#define G_BM 128
#define G_BN 128
#define G_BK 32
#define GA_STRIDE 36
#define GB_STRIDE 132
#define G_STAGE_WORDS (G_BM * GA_STRIDE + G_BK * GB_STRIDE)   // 8832
#define G_SMEM_BYTES  (2 * G_STAGE_WORDS * 4)                 // 70,656 B

__device__ float g_xh[(size_t)BATCH * TSEQ * DIM];
__device__ unsigned g_count;
__device__ unsigned g_sense;

__device__ __forceinline__ uint32_t f2tf32(float x) {
    uint32_t r;
    asm("cvt.rna.tf32.f32 %0, %1;" : "=r"(r) : "f"(x));
    return r;
}

__device__ __forceinline__ void mma_tf32(float* d,
                                         uint32_t a0, uint32_t a1, uint32_t a2, uint32_t a3,
                                         uint32_t b0, uint32_t b1) {
    asm volatile(
        "mma.sync.aligned.m16n8k8.row.col.f32.tf32.tf32.f32 "
        "{%0,%1,%2,%3}, {%4,%5,%6,%7}, {%8,%9}, {%0,%1,%2,%3};\n"
        : "+f"(d[0]), "+f"(d[1]), "+f"(d[2]), "+f"(d[3])
        : "r"(a0), "r"(a1), "r"(a2), "r"(a3), "r"(b0), "r"(b1));
}

__device__ __forceinline__ float sigmoidf_fast(float z) {
    return 1.0f / (1.0f + __expf(-z));
}

__device__ __forceinline__ void cp16(uint32_t smem_addr, const void* gsrc) {
    asm volatile("cp.async.cg.shared.global [%0], [%1], 16;\n"
                 :: "r"(smem_addr), "l"(gsrc));
}
__device__ __forceinline__ void cp_commit() {
    asm volatile("cp.async.commit_group;\n" ::: "memory");
}
template <int N>
__device__ __forceinline__ void cp_wait() {
    asm volatile("cp.async.wait_group %0;\n" :: "n"(N) : "memory");
}

// ---------------------------------------------------------------------------
// Phase 1: xh = X[32768,1024] @ W[1024,1024], raw-f32 tf32 mma, 2-stage cp.async.
// CTA 128x128, BK=32, 8 warps: warp grid 2(M)x4(N), warp tile 64x32.
// ---------------------------------------------------------------------------
__global__ __launch_bounds__(256) void gemm_xh_kernel(const float* __restrict__ X,
                                                      const float* __restrict__ W) {
    extern __shared__ uint32_t gsm[];

    const int tid  = threadIdx.x;
    const int lane = tid & 31;
    const int wid  = tid >> 5;
    const int bm   = blockIdx.y * G_BM;
    const int bn   = blockIdx.x * G_BN;
    const int wm   = (wid & 1) * 64;
    const int wn   = (wid >> 1) * 32;
    const int gid  = lane >> 2;
    const int tg   = lane & 3;

    // per-stage pointers (word offsets)
    auto As = [&](int s) { return gsm + s * G_STAGE_WORDS; };
    auto Bs = [&](int s) { return gsm + s * G_STAGE_WORDS + G_BM * GA_STRIDE; };

    // cp.async issue for K-tile starting at k0 into stage s
    auto issue = [&](int k0, int s) {
        uint32_t abase = (uint32_t)__cvta_generic_to_shared(As(s));
        uint32_t bbase = (uint32_t)__cvta_generic_to_shared(Bs(s));
        // A: 128x32 floats = 1024 float4, 4 per thread
        #pragma unroll
        for (int i = 0; i < 4; i++) {
            int idx = tid + i * 256;
            int r = idx >> 3;
            int c = (idx & 7) * 4;
            cp16(abase + (r * GA_STRIDE + c) * 4,
                 X + (size_t)(bm + r) * DIM + k0 + c);
        }
        // B: 32x128 floats = 1024 float4, 4 per thread
        #pragma unroll
        for (int i = 0; i < 4; i++) {
            int idx = tid + i * 256;
            int r = idx >> 5;
            int c = (idx & 31) * 4;
            cp16(bbase + (r * GB_STRIDE + c) * 4,
                 W + (size_t)(k0 + r) * DIM + bn + c);
        }
        cp_commit();
    };

    float acc[4][4][4];
    #pragma unroll
    for (int mt = 0; mt < 4; mt++)
        #pragma unroll
        for (int nt = 0; nt < 4; nt++)
            #pragma unroll
            for (int i = 0; i < 4; i++) acc[mt][nt][i] = 0.0f;

    issue(0, 0);
    issue(G_BK, 1);

    const int NKITER = DIM / G_BK;   // 32
    for (int kb = 0; kb < NKITER; kb++) {
        if (kb < NKITER - 1) cp_wait<1>(); else cp_wait<0>();
        __syncthreads();

        const uint32_t* A = As(kb & 1);
        const uint32_t* B = Bs(kb & 1);

        #pragma unroll
        for (int k8 = 0; k8 < G_BK; k8 += 8) {
            uint32_t a[4][4], b[4][2];
            #pragma unroll
            for (int mt = 0; mt < 4; mt++) {
                int r = (wm + mt * 16 + gid) * GA_STRIDE;
                a[mt][0] = A[r + k8 + tg];
                a[mt][1] = A[r + 8 * GA_STRIDE + k8 + tg];
                a[mt][2] = A[r + k8 + tg + 4];
                a[mt][3] = A[r + 8 * GA_STRIDE + k8 + tg + 4];
            }
            #pragma unroll
            for (int nt = 0; nt < 4; nt++) {
                int c = wn + nt * 8 + gid;
                b[nt][0] = B[(k8 + tg) * GB_STRIDE + c];
                b[nt][1] = B[(k8 + tg + 4) * GB_STRIDE + c];
            }
            #pragma unroll
            for (int mt = 0; mt < 4; mt++)
                #pragma unroll
                for (int nt = 0; nt < 4; nt++)
                    mma_tf32(acc[mt][nt], a[mt][0], a[mt][1], a[mt][2], a[mt][3],
                             b[nt][0], b[nt][1]);
        }
        __syncthreads();
        if (kb + 2 < NKITER) issue((kb + 2) * G_BK, kb & 1);
    }

    #pragma unroll
    for (int mt = 0; mt < 4; mt++) {
        #pragma unroll
        for (int nt = 0; nt < 4; nt++) {
            int r = bm + wm + mt * 16 + gid;
            int c = bn + wn + nt * 8 + tg * 2;
            *(float2*)(&g_xh[(size_t)r * DIM + c]) =
                make_float2(acc[mt][nt][0], acc[mt][nt][1]);
            *(float2*)(&g_xh[(size_t)(r + 8) * DIM + c]) =
                make_float2(acc[mt][nt][2], acc[mt][nt][3]);
        }
    }
}

// ---------------------------------------------------------------------------
// Phase 2: persistent recurrence. 64 CTAs x 256 thr. CTA owns 16 N-cols.
// 2-way K-split: warps 0-3 (wm = w*16) cover K [0,512), warps 4-7 K [512,1024).
// Warp tile 16x16 (2 n8 frags). 4 rounds/step, chunk-pair per round, 4-slot ring.
// ---------------------------------------------------------------------------
__global__ __launch_bounds__(256, 1) void rnn_persistent(const float* __restrict__ Wr,
                                                         float* __restrict__ OUT) {
    extern __shared__ uint32_t smem[];
    uint32_t* Bsm = smem;                 // [NTILE][BS_STRIDE], tf32 Wr slice
    uint32_t* Asm = smem + BS_WORDS;      // 4 slots of [64][AS_STRIDE]

    const int tid  = threadIdx.x;
    const int lane = tid & 31;
    const int wid  = tid >> 5;
    const int bn   = blockIdx.x * NTILE;
    const int wm   = (wid & 3) * 16;      // M rows per warp
    const int khalf = (wid >> 2);         // 0: K[0,512), 1: K[512,1024)
    const int gid  = lane >> 2;
    const int tg   = lane & 3;

    // Wr slice -> SMEM transposed [n][k], RNA tf32 (done once)
    for (int idx = tid; idx < NTILE * DIM; idx += 256) {
        int n = idx & (NTILE - 1);
        int k = idx >> 4;
        Bsm[n * BS_STRIDE + k] = f2tf32(Wr[(size_t)k * DIM + bn + n]);
    }
    __syncthreads();

    const int arow = (wm + gid) * AS_STRIDE;
    const uint32_t asm_base = (uint32_t)__cvta_generic_to_shared(Asm);

    for (int t = 0; t < TSEQ; t++) {
        float acc[2][4];
        #pragma unroll
        for (int nt = 0; nt < 2; nt++)
            #pragma unroll
            for (int i = 0; i < 4; i++) acc[nt][i] = 0.0f;

        if (t > 0) {
            const float* Hprev = OUT + (size_t)(t - 1) * DIM;  // + r*TSEQ*DIM

            // issue chunk pair (r, r+4) for round r into slots (2r&3, 2r+1&3)
            auto issue_round = [&](int r) {
                #pragma unroll
                for (int half = 0; half < 2; half++) {
                    int chunk = r + half * 4;
                    int slot  = (2 * r + half) & 3;
                    int k0 = chunk * BK;
                    uint32_t sbase = asm_base + slot * AS_SLOT * 4;
                    #pragma unroll
                    for (int i = 0; i < 8; i++) {
                        int idx = tid + i * 256;
                        int rr = idx >> 5;
                        int c4 = (idx & 31) * 4;
                        cp16(sbase + (rr * AS_STRIDE + c4) * 4,
                             Hprev + (size_t)rr * (TSEQ * DIM) + k0 + c4);
                    }
                }
                cp_commit();
            };

            issue_round(0);
            issue_round(1);

            #pragma unroll
            for (int r = 0; r < 4; r++) {
                if (r < 3) cp_wait<1>(); else cp_wait<0>();
                __syncthreads();

                const int slot = (2 * r + khalf) & 3;
                const uint32_t* Ab = Asm + slot * AS_SLOT;
                const int kbase = khalf * 512 + r * BK;

                #pragma unroll
                for (int k8 = 0; k8 < BK; k8 += 8) {
                    uint32_t a0 = Ab[arow + k8 + tg];
                    uint32_t a1 = Ab[arow + 8 * AS_STRIDE + k8 + tg];
                    uint32_t a2 = Ab[arow + k8 + tg + 4];
                    uint32_t a3 = Ab[arow + 8 * AS_STRIDE + k8 + tg + 4];
                    #pragma unroll
                    for (int nt = 0; nt < 2; nt++) {
                        int n = nt * 8 + gid;
                        uint32_t b0 = Bsm[n * BS_STRIDE + kbase + k8 + tg];
                        uint32_t b1 = Bsm[n * BS_STRIDE + kbase + k8 + tg + 4];
                        mma_tf32(acc[nt], a0, a1, a2, a3, b0, b1);
                    }
                }
                __syncthreads();
                if (r + 2 < 4) issue_round(r + 2);
            }
        }

        // 2-way K reduction: warps 4-7 hand partials to warps 0-3.
        {
            float* red = (float*)Asm;   // slots are dead here
            if (khalf == 1) {
                float4* dst = (float4*)&red[(((wid - 4) * 32 + lane) * 8)];
                dst[0] = make_float4(acc[0][0], acc[0][1], acc[0][2], acc[0][3]);
                dst[1] = make_float4(acc[1][0], acc[1][1], acc[1][2], acc[1][3]);
            }
            __syncthreads();
            if (khalf == 0) {
                const float4* src = (const float4*)&red[((wid * 32 + lane) * 8)];
                float4 p0 = src[0], p1 = src[1];
                acc[0][0] += p0.x; acc[0][1] += p0.y; acc[0][2] += p0.z; acc[0][3] += p0.w;
                acc[1][0] += p1.x; acc[1][1] += p1.y; acc[1][2] += p1.z; acc[1][3] += p1.w;

                // epilogue: h = sigmoid(acc + xh), write OUT[b,t,:]
                int rb = wm + gid;
                #pragma unroll
                for (int nt = 0; nt < 2; nt++) {
                    int cb = bn + nt * 8 + 2 * tg;
                    size_t o0 = ((size_t)rb * TSEQ + t) * DIM + cb;
                    size_t o8 = o0 + (size_t)8 * TSEQ * DIM;
                    float2 xh0 = *(const float2*)&g_xh[o0];
                    float2 xh1 = *(const float2*)&g_xh[o8];
                    *(float2*)&OUT[o0] = make_float2(sigmoidf_fast(acc[nt][0] + xh0.x),
                                                     sigmoidf_fast(acc[nt][1] + xh0.y));
                    *(float2*)&OUT[o8] = make_float2(sigmoidf_fast(acc[nt][2] + xh1.x),
                                                     sigmoidf_fast(acc[nt][3] + xh1.y));
                }
            }
        }

        // grid barrier (sense-reversing; state returns to initial after 512 rounds)
        __syncthreads();
        if (tid == 0) {
            unsigned ns = ((unsigned)t & 1u) ^ 1u;
            unsigned old;
            asm volatile("atom.acq_rel.gpu.global.add.u32 %0, [%1], %2;"
                         : "=r"(old) : "l"(&g_count), "r"(1u) : "memory");
            if (old == NCTA - 1) {
                asm volatile("st.relaxed.gpu.global.u32 [%0], %1;"
                             :: "l"(&g_count), "r"(0u) : "memory");
                asm volatile("st.release.gpu.global.u32 [%0], %1;"
                             :: "l"(&g_sense), "r"(ns) : "memory");
            } else {
                unsigned v;
                do {
                    asm volatile("ld.acquire.gpu.global.u32 %0, [%1];"
                                 : "=r"(v) : "l"(&g_sense) : "memory");
                } while (v != ns);
            }
        }
        __syncthreads();
    }
}

// ---------------------------------------------------------------------------
extern "C" void kernel_launch(void* const* d_in, const int* in_sizes, int n_in,
                              void* d_out, int out_size) {
    const float* x  = (const float*)d_in[0];  // [64, 512, 1024]
    const float* w  = (const float*)d_in[1];  // [1024, 1024]
    const float* wr = (const float*)d_in[2];  // [1024, 1024]
    float* out = (float*)d_out;               // [64, 512, 1024]

    cudaFuncSetAttribute(gemm_xh_kernel,
                         cudaFuncAttributeMaxDynamicSharedMemorySize, G_SMEM_BYTES);
    cudaFuncSetAttribute(rnn_persistent,
                         cudaFuncAttributeMaxDynamicSharedMemorySize, P2_SMEM_BYTES);

    dim3 grid1(DIM / G_BN, (BATCH * TSEQ) / G_BM);   // (8, 256)
    gemm_xh_kernel<<<grid1, 256, G_SMEM_BYTES>>>(x, w);

    rnn_persistent<<<NCTA, 256, P2_SMEM_BYTES>>>(wr, out);
}

// round 5
// speedup vs baseline: 6.1113x; 1.1284x over previous
#include <cuda_runtime.h>
#include <cuda_bf16.h>
#include <cstdint>

// ---------------------------------------------------------------------------
// RNN: out[b,t,:] = sigmoid(x@K + h_{t-1}@Wr),  B=64, T=512, D=H=1024
// Phase 1: xh = x @ kernel  -- double-buffered cp.async TF32 mma GEMM
// Phase 2: ONE persistent kernel, 64 CTAs, 512 steps, grid barriers.
//   Warp grid 2(M:32 rows)x4(K:256 cols). Each warp streams ITS OWN A-slice
//   through a private 2-buffer cp.async ring (per-warp waits only).
//   4-way K reduction via SMEM scratch + flat epilogue pass.
// ---------------------------------------------------------------------------

#define BATCH 64
#define TSEQ  512
#define DIM   1024

// ---- phase 2 geometry ----
#define NCTA   64
#define NTILE  16
#define BS_STRIDE 1028                // 1024 + 4 (stride%32 = 4 -> conflict-free)
#define BS_WORDS  (NTILE * BS_STRIDE) // 16448
#define A_STRIDE  68                  // 64 + 4 pad
#define ABUF_WORDS (32 * A_STRIDE)    // one chunk buffer: 32 rows x 64 cols
#define A_REGION_WORDS (8 * 2 * ABUF_WORDS)   // 34816
#define P2_SMEM_BYTES ((BS_WORDS + A_REGION_WORDS) * 4)   // 205,056 B

// ---- phase 1 geometry ----
#define G_BM 128
#define G_BN 128
#define G_BK 32
#define GA_STRIDE 36
#define GB_STRIDE 132
#define G_STAGE_WORDS (G_BM * GA_STRIDE + G_BK * GB_STRIDE)
#define G_SMEM_BYTES  (2 * G_STAGE_WORDS * 4)

__device__ float g_xh[(size_t)BATCH * TSEQ * DIM];
__device__ unsigned g_count;
__device__ unsigned g_sense;

__device__ __forceinline__ uint32_t f2tf32(float x) {
    uint32_t r;
    asm("cvt.rna.tf32.f32 %0, %1;" : "=r"(r) : "f"(x));
    return r;
}

__device__ __forceinline__ void mma_tf32(float* d,
                                         uint32_t a0, uint32_t a1, uint32_t a2, uint32_t a3,
                                         uint32_t b0, uint32_t b1) {
    asm volatile(
        "mma.sync.aligned.m16n8k8.row.col.f32.tf32.tf32.f32 "
        "{%0,%1,%2,%3}, {%4,%5,%6,%7}, {%8,%9}, {%0,%1,%2,%3};\n"
        : "+f"(d[0]), "+f"(d[1]), "+f"(d[2]), "+f"(d[3])
        : "r"(a0), "r"(a1), "r"(a2), "r"(a3), "r"(b0), "r"(b1));
}

__device__ __forceinline__ float sigmoidf_fast(float z) {
    return 1.0f / (1.0f + __expf(-z));
}

__device__ __forceinline__ void cp16(uint32_t smem_addr, const void* gsrc) {
    asm volatile("cp.async.cg.shared.global [%0], [%1], 16;\n"
                 :: "r"(smem_addr), "l"(gsrc));
}
__device__ __forceinline__ void cp_commit() {
    asm volatile("cp.async.commit_group;\n" ::: "memory");
}
template <int N>
__device__ __forceinline__ void cp_wait() {
    asm volatile("cp.async.wait_group %0;\n" :: "n"(N) : "memory");
}

// ---------------------------------------------------------------------------
// Phase 1: xh = X[32768,1024] @ W[1024,1024]  (unchanged from R3 - passing)
// ---------------------------------------------------------------------------
__global__ __launch_bounds__(256) void gemm_xh_kernel(const float* __restrict__ X,
                                                      const float* __restrict__ W) {
    extern __shared__ uint32_t gsm[];

    const int tid  = threadIdx.x;
    const int lane = tid & 31;
    const int wid  = tid >> 5;
    const int bm   = blockIdx.y * G_BM;
    const int bn   = blockIdx.x * G_BN;
    const int wm   = (wid & 1) * 64;
    const int wn   = (wid >> 1) * 32;
    const int gid  = lane >> 2;
    const int tg   = lane & 3;

    auto As = [&](int s) { return gsm + s * G_STAGE_WORDS; };
    auto Bs = [&](int s) { return gsm + s * G_STAGE_WORDS + G_BM * GA_STRIDE; };

    auto issue = [&](int k0, int s) {
        uint32_t abase = (uint32_t)__cvta_generic_to_shared(As(s));
        uint32_t bbase = (uint32_t)__cvta_generic_to_shared(Bs(s));
        #pragma unroll
        for (int i = 0; i < 4; i++) {
            int idx = tid + i * 256;
            int r = idx >> 3;
            int c = (idx & 7) * 4;
            cp16(abase + (r * GA_STRIDE + c) * 4,
                 X + (size_t)(bm + r) * DIM + k0 + c);
        }
        #pragma unroll
        for (int i = 0; i < 4; i++) {
            int idx = tid + i * 256;
            int r = idx >> 5;
            int c = (idx & 31) * 4;
            cp16(bbase + (r * GB_STRIDE + c) * 4,
                 W + (size_t)(k0 + r) * DIM + bn + c);
        }
        cp_commit();
    };

    float acc[4][4][4];
    #pragma unroll
    for (int mt = 0; mt < 4; mt++)
        #pragma unroll
        for (int nt = 0; nt < 4; nt++)
            #pragma unroll
            for (int i = 0; i < 4; i++) acc[mt][nt][i] = 0.0f;

    issue(0, 0);
    issue(G_BK, 1);

    const int NKITER = DIM / G_BK;
    for (int kb = 0; kb < NKITER; kb++) {
        if (kb < NKITER - 1) cp_wait<1>(); else cp_wait<0>();
        __syncthreads();

        const uint32_t* A = As(kb & 1);
        const uint32_t* B = Bs(kb & 1);

        #pragma unroll
        for (int k8 = 0; k8 < G_BK; k8 += 8) {
            uint32_t a[4][4], b[4][2];
            #pragma unroll
            for (int mt = 0; mt < 4; mt++) {
                int r = (wm + mt * 16 + gid) * GA_STRIDE;
                a[mt][0] = A[r + k8 + tg];
                a[mt][1] = A[r + 8 * GA_STRIDE + k8 + tg];
                a[mt][2] = A[r + k8 + tg + 4];
                a[mt][3] = A[r + 8 * GA_STRIDE + k8 + tg + 4];
            }
            #pragma unroll
            for (int nt = 0; nt < 4; nt++) {
                int c = wn + nt * 8 + gid;
                b[nt][0] = B[(k8 + tg) * GB_STRIDE + c];
                b[nt][1] = B[(k8 + tg + 4) * GB_STRIDE + c];
            }
            #pragma unroll
            for (int mt = 0; mt < 4; mt++)
                #pragma unroll
                for (int nt = 0; nt < 4; nt++)
                    mma_tf32(acc[mt][nt], a[mt][0], a[mt][1], a[mt][2], a[mt][3],
                             b[nt][0], b[nt][1]);
        }
        __syncthreads();
        if (kb + 2 < NKITER) issue((kb + 2) * G_BK, kb & 1);
    }

    #pragma unroll
    for (int mt = 0; mt < 4; mt++) {
        #pragma unroll
        for (int nt = 0; nt < 4; nt++) {
            int r = bm + wm + mt * 16 + gid;
            int c = bn + wn + nt * 8 + tg * 2;
            *(float2*)(&g_xh[(size_t)r * DIM + c]) =
                make_float2(acc[mt][nt][0], acc[mt][nt][1]);
            *(float2*)(&g_xh[(size_t)(r + 8) * DIM + c]) =
                make_float2(acc[mt][nt][2], acc[mt][nt][3]);
        }
    }
}

// ---------------------------------------------------------------------------
// Phase 2: persistent recurrence. 64 CTAs x 256 thr (8 warps).
// Warp w: rows [wm2, wm2+32) (wm2=(w&1)*32), K quarter kq=w>>1 (256 cols),
// all 16 N cols. Private double-buffered chunk ring (4 chunks of 32x64).
// After compute: partials -> scratch (aliases A rings) -> flat epilogue.
// ---------------------------------------------------------------------------
__global__ __launch_bounds__(256, 1) void rnn_persistent(const float* __restrict__ Wr,
                                                         float* __restrict__ OUT) {
    extern __shared__ uint32_t smem[];
    uint32_t* Bsm  = smem;                 // [16][BS_STRIDE] tf32 Wr (transposed)
    uint32_t* Abuf = smem + BS_WORDS;      // 8 warps x 2 bufs x [32][A_STRIDE]
    float*    Scr  = (float*)Abuf;         // reduction scratch (aliases rings)

    const int tid  = threadIdx.x;
    const int lane = tid & 31;
    const int wid  = tid >> 5;
    const int bn   = blockIdx.x * NTILE;
    const int wm2  = (wid & 1) * 32;       // M rows base
    const int kq   = wid >> 1;             // K quarter 0..3
    const int kbase = kq * 256;
    const int gid  = lane >> 2;
    const int tg   = lane & 3;

    // Wr slice -> SMEM transposed [n][k], RNA tf32 (once)
    for (int idx = tid; idx < NTILE * DIM; idx += 256) {
        int n = idx & (NTILE - 1);
        int k = idx >> 4;
        Bsm[n * BS_STRIDE + k] = f2tf32(Wr[(size_t)k * DIM + bn + n]);
    }
    __syncthreads();

    const uint32_t* Aw = Abuf + wid * 2 * ABUF_WORDS;
    const uint32_t warp_sb = (uint32_t)__cvta_generic_to_shared(Abuf)
                           + wid * 2 * ABUF_WORDS * 4;

    for (int t = 0; t < TSEQ; t++) {
        float acc[2][2][2][4];   // [chain][mt][nt][frag]
        #pragma unroll
        for (int ch = 0; ch < 2; ch++)
            #pragma unroll
            for (int mt = 0; mt < 2; mt++)
                #pragma unroll
                for (int nt = 0; nt < 2; nt++)
                    #pragma unroll
                    for (int i = 0; i < 4; i++) acc[ch][mt][nt][i] = 0.0f;

        if (t > 0) {
            const float* Hprev = OUT + (size_t)(t - 1) * DIM;

            // issue chunk c (32 rows x 64 floats = 16 cp16/lane) into buf c&1
            auto issue = [&](int c) {
                const int k0 = kbase + c * 64;
                const uint32_t base = warp_sb + (c & 1) * ABUF_WORDS * 4;
                #pragma unroll
                for (int i = 0; i < 16; i++) {
                    int idx = lane + i * 32;
                    int r  = idx >> 4;        // 0..31
                    int c4 = idx & 15;        // 0..15
                    cp16(base + (r * A_STRIDE + c4 * 4) * 4,
                         Hprev + (size_t)(wm2 + r) * (TSEQ * DIM) + k0 + c4 * 4);
                }
                cp_commit();
            };

            issue(0);
            issue(1);

            #pragma unroll
            for (int c = 0; c < 4; c++) {
                if (c < 3) cp_wait<1>(); else cp_wait<0>();
                __syncwarp();

                const uint32_t* Ab = Aw + (c & 1) * ABUF_WORDS;
                const int kb = kbase + c * 64;

                #pragma unroll
                for (int k8i = 0; k8i < 8; k8i++) {
                    const int kk = k8i * 8;
                    const int ch = k8i & 1;
                    uint32_t a[2][4];
                    #pragma unroll
                    for (int mt = 0; mt < 2; mt++) {
                        int lr = (mt * 16 + gid) * A_STRIDE;
                        a[mt][0] = Ab[lr + kk + tg];
                        a[mt][1] = Ab[lr + 8 * A_STRIDE + kk + tg];
                        a[mt][2] = Ab[lr + kk + tg + 4];
                        a[mt][3] = Ab[lr + 8 * A_STRIDE + kk + tg + 4];
                    }
                    #pragma unroll
                    for (int nt = 0; nt < 2; nt++) {
                        int n = nt * 8 + gid;
                        uint32_t b0 = Bsm[n * BS_STRIDE + kb + kk + tg];
                        uint32_t b1 = Bsm[n * BS_STRIDE + kb + kk + tg + 4];
                        #pragma unroll
                        for (int mt = 0; mt < 2; mt++)
                            mma_tf32(acc[ch][mt][nt], a[mt][0], a[mt][1],
                                     a[mt][2], a[mt][3], b0, b1);
                    }
                }
                if (c + 2 < 4) issue(c + 2);
            }
        }

        // fold chains
        float accf[2][2][4];
        #pragma unroll
        for (int mt = 0; mt < 2; mt++)
            #pragma unroll
            for (int nt = 0; nt < 2; nt++)
                #pragma unroll
                for (int i = 0; i < 4; i++)
                    accf[mt][nt][i] = acc[0][mt][nt][i] + acc[1][mt][nt][i];

        // all compute done before scratch (aliases A rings)
        __syncthreads();

        // partial store: P[kq][row 0..63][col 0..15]
        #pragma unroll
        for (int mt = 0; mt < 2; mt++) {
            int rg = wm2 + mt * 16 + gid;
            #pragma unroll
            for (int nt = 0; nt < 2; nt++) {
                int off = kq * 1024 + rg * 16 + nt * 8 + tg * 2;
                *(float2*)&Scr[off]          = make_float2(accf[mt][nt][0], accf[mt][nt][1]);
                *(float2*)&Scr[off + 8 * 16] = make_float2(accf[mt][nt][2], accf[mt][nt][3]);
            }
        }
        __syncthreads();

        // flat epilogue: 256 threads x 4 outputs (row = tid>>2, col4 = (tid&3)*4)
        {
            int o   = tid * 4;
            int row = o >> 4;
            int col = o & 15;
            float4 s0 = *(const float4*)&Scr[o];
            float4 s1 = *(const float4*)&Scr[1024 + o];
            float4 s2 = *(const float4*)&Scr[2048 + o];
            float4 s3 = *(const float4*)&Scr[3072 + o];
            float sx = s0.x + s1.x + s2.x + s3.x;
            float sy = s0.y + s1.y + s2.y + s3.y;
            float sz = s0.z + s1.z + s2.z + s3.z;
            float sw = s0.w + s1.w + s2.w + s3.w;
            size_t go = ((size_t)row * TSEQ + t) * DIM + bn + col;
            float4 xh = *(const float4*)&g_xh[go];
            float4 h;
            h.x = sigmoidf_fast(sx + xh.x);
            h.y = sigmoidf_fast(sy + xh.y);
            h.z = sigmoidf_fast(sz + xh.z);
            h.w = sigmoidf_fast(sw + xh.w);
            *(float4*)&OUT[go] = h;
        }

        // grid barrier (sense-reversing; state invariant after 512 rounds)
        __syncthreads();
        if (tid == 0) {
            unsigned ns = ((unsigned)t & 1u) ^ 1u;
            unsigned old;
            asm volatile("atom.acq_rel.gpu.global.add.u32 %0, [%1], %2;"
                         : "=r"(old) : "l"(&g_count), "r"(1u) : "memory");
            if (old == NCTA - 1) {
                asm volatile("st.relaxed.gpu.global.u32 [%0], %1;"
                             :: "l"(&g_count), "r"(0u) : "memory");
                asm volatile("st.release.gpu.global.u32 [%0], %1;"
                             :: "l"(&g_sense), "r"(ns) : "memory");
            } else {
                unsigned v;
                do {
                    asm volatile("ld.acquire.gpu.global.u32 %0, [%1];"
                                 : "=r"(v) : "l"(&g_sense) : "memory");
                } while (v != ns);
            }
        }
        __syncthreads();
    }
}

// ---------------------------------------------------------------------------
extern "C" void kernel_launch(void* const* d_in, const int* in_sizes, int n_in,
                              void* d_out, int out_size) {
    const float* x  = (const float*)d_in[0];  // [64, 512, 1024]
    const float* w  = (const float*)d_in[1];  // [1024, 1024]
    const float* wr = (const float*)d_in[2];  // [1024, 1024]
    float* out = (float*)d_out;               // [64, 512, 1024]

    cudaFuncSetAttribute(gemm_xh_kernel,
                         cudaFuncAttributeMaxDynamicSharedMemorySize, G_SMEM_BYTES);
    cudaFuncSetAttribute(rnn_persistent,
                         cudaFuncAttributeMaxDynamicSharedMemorySize, P2_SMEM_BYTES);

    dim3 grid1(DIM / G_BN, (BATCH * TSEQ) / G_BM);
    gemm_xh_kernel<<<grid1, 256, G_SMEM_BYTES>>>(x, w);

    rnn_persistent<<<NCTA, 256, P2_SMEM_BYTES>>>(wr, out);
}